// round 16
// baseline (speedup 1.0000x reference)
#include <cuda_runtime.h>
#include <math.h>

#define NB 8
#define IMGW 120
#define TGRID 1024
#define PPTS 1024

#define C1_THREADS (NB * 2 * 57 * 57)
#define C1_BLOCKS ((C1_THREADS + 255) / 256)     // 204 (4 oc per thread)
#define C2_THREADS (NB * 10 * 26 * 26)
#define C2_BLOCKS ((C2_THREADS + 255) / 256)     // 212
#define FC1_BLOCKS 256
#define PREF_BLOCKS 8

#define FILL_A (11 * 64)    // planes 0-10
#define FILL_B (8 * 64)     // planes 11-18
#define FILL_C (5 * 64)     // planes 19-23

#define H1_STRIDE 58

// scratch (no allocations allowed)
__device__ float g_h1[NB * 8 * 57 * H1_STRIDE];
__device__ float g_h2[NB * 10 * 26 * 26];
__device__ float g_z[NB * 32];
__device__ int   g_cnt[NB];                       // zero-init; self-resetting
__device__ float g_sink;                          // prefetch sink

// proven R10 fill: 64 blocks per plane, strided float4 stores
__device__ __forceinline__ void fill_planes(const float* __restrict__ x,
                                            float* __restrict__ out96,
                                            int fblk, int plane_base) {
    int plane = plane_base + (fblk >> 6);
    if (plane >= 24) return;
    int b = fblk & 63;
    const float* xb = x + (size_t)plane * IMGW * IMGW;
    float cst = 0.25f * (__ldg(xb + 59 * IMGW + 59) + __ldg(xb + 59 * IMGW + 60) +
                         __ldg(xb + 60 * IMGW + 59) + __ldg(xb + 60 * IMGW + 60));
    float4 v = make_float4(cst, cst, cst, cst);
    float4* o = reinterpret_cast<float4*>(out96 + (size_t)plane * TGRID * TGRID);
    const int stride = 64 * 256;
#pragma unroll 4
    for (int i = b * 256 + threadIdx.x; i < (TGRID * TGRID / 4); i += stride)
        o[i] = v;
}

// ---------------- kernel A: conv1 (4 oc/thread) || fill planes 0-10 ----------
__global__ __launch_bounds__(256) void kernelA(const float* __restrict__ x,
                                               const float* __restrict__ w,
                                               const float* __restrict__ b,
                                               float* __restrict__ out96) {
    if (blockIdx.x >= C1_BLOCKS) {
        fill_planes(x, out96, blockIdx.x - C1_BLOCKS, 0);
        return;
    }

    __shared__ float ws[8 * 3 * 49];
    __shared__ float bs[8];
    for (int i = threadIdx.x; i < 8 * 3 * 49; i += 256) ws[i] = w[i];
    if (threadIdx.x < 8) bs[threadIdx.x] = b[threadIdx.x];
    __syncthreads();

    int idx = blockIdx.x * 256 + threadIdx.x;
    if (idx >= C1_THREADS) return;
    int px  = idx % 57;
    int py  = (idx / 57) % 57;
    int ocg = (idx / 3249) & 1;
    int n   = idx / 6498;

    float acc[4][4];
#pragma unroll
    for (int oc = 0; oc < 4; oc++)
        acc[oc][0] = acc[oc][1] = acc[oc][2] = acc[oc][3] = 0.f;

    const float* xb = x + (size_t)n * 3 * IMGW * IMGW;
    for (int ic = 0; ic < 3; ic++) {
        const float* xc = xb + ic * IMGW * IMGW + (2 * py) * IMGW + 2 * px;
#pragma unroll
        for (int wy = 0; wy < 8; wy++) {
            const float2* row = reinterpret_cast<const float2*>(xc + wy * IMGW);
            float v[8];
#pragma unroll
            for (int j = 0; j < 4; j++) {
                float2 t = __ldg(row + j);
                v[2 * j] = t.x; v[2 * j + 1] = t.y;
            }
#pragma unroll
            for (int oc = 0; oc < 4; oc++) {
                const float* wr = ws + ((ocg * 4 + oc) * 3 + ic) * 49;
                if (wy < 7) {
#pragma unroll
                    for (int kx = 0; kx < 7; kx++) {
                        float wv = wr[wy * 7 + kx];
                        acc[oc][0] = fmaf(wv, v[kx], acc[oc][0]);
                        acc[oc][1] = fmaf(wv, v[kx + 1], acc[oc][1]);
                    }
                }
                if (wy >= 1) {
#pragma unroll
                    for (int kx = 0; kx < 7; kx++) {
                        float wv = wr[(wy - 1) * 7 + kx];
                        acc[oc][2] = fmaf(wv, v[kx], acc[oc][2]);
                        acc[oc][3] = fmaf(wv, v[kx + 1], acc[oc][3]);
                    }
                }
            }
        }
    }
#pragma unroll
    for (int oc = 0; oc < 4; oc++) {
        int woc = ocg * 4 + oc;
        float m = fmaxf(fmaxf(acc[oc][0], acc[oc][1]), fmaxf(acc[oc][2], acc[oc][3]));
        g_h1[((n * 8 + woc) * 57 + py) * H1_STRIDE + px] = fmaxf(m + bs[woc], 0.f);
    }
}

// -------- kernel B: conv2 || fill planes 11-18 || prefetch fw1 to L2 ---------
__global__ __launch_bounds__(256) void kernelB(const float* __restrict__ x,
                                               const float* __restrict__ w,
                                               const float* __restrict__ b,
                                               const float* __restrict__ fw1,
                                               float* __restrict__ out96) {
    if (blockIdx.x >= C2_BLOCKS + FILL_B) {
        int pb = blockIdx.x - (C2_BLOCKS + FILL_B);
        const float4* f4 = reinterpret_cast<const float4*>(fw1);
        float s = 0.f;
        for (int i = pb * 256 + threadIdx.x; i < 54080; i += PREF_BLOCKS * 256)
            s += __ldg(&f4[i].x);
        if (s == -12345.678f) g_sink = s;   // never true; keeps loads live
        return;
    }
    if (blockIdx.x >= C2_BLOCKS) {
        fill_planes(x, out96, blockIdx.x - C2_BLOCKS, 11);
        return;
    }

    __shared__ float ws[10 * 8 * 25];
    __shared__ float bs[10];
    for (int i = threadIdx.x; i < 2000; i += 256) ws[i] = w[i];
    if (threadIdx.x < 10) bs[threadIdx.x] = b[threadIdx.x];
    __syncthreads();

    int idx = blockIdx.x * 256 + threadIdx.x;
    if (idx >= C2_THREADS) return;
    int px = idx % 26;
    int py = (idx / 26) % 26;
    int oc = (idx / 676) % 10;
    int n  = idx / 6760;

    float a0 = 0.f, a1 = 0.f, a2 = 0.f, a3 = 0.f;
    for (int ic = 0; ic < 8; ic++) {
        const float* xc = g_h1 + ((n * 8 + ic) * 57 + 2 * py) * H1_STRIDE + 2 * px;
        const float* wr = ws + (oc * 8 + ic) * 25;
#pragma unroll
        for (int wy = 0; wy < 6; wy++) {
            const float2* row = reinterpret_cast<const float2*>(xc + wy * H1_STRIDE);
            float v[6];
#pragma unroll
            for (int j = 0; j < 3; j++) {
                float2 t = row[j];
                v[2 * j] = t.x; v[2 * j + 1] = t.y;
            }
            if (wy < 5) {
#pragma unroll
                for (int kx = 0; kx < 5; kx++) {
                    float wv = wr[wy * 5 + kx];
                    a0 = fmaf(wv, v[kx], a0);
                    a1 = fmaf(wv, v[kx + 1], a1);
                }
            }
            if (wy >= 1) {
#pragma unroll
                for (int kx = 0; kx < 5; kx++) {
                    float wv = wr[(wy - 1) * 5 + kx];
                    a2 = fmaf(wv, v[kx], a2);
                    a3 = fmaf(wv, v[kx + 1], a3);
                }
            }
        }
    }
    float m = fmaxf(fmaxf(a0, a1), fmaxf(a2, a3));
    g_h2[idx] = fmaxf(m + bs[oc], 0.f);
}

// ---- kernel C: fc1 (256 blks) + fill planes 19-23 (320 blks); unique
// ---- last-arriving block per image runs fc2 + Rodrigues + scatter.
// ---- Targets: n<6 -> 32 fc1 blocks; n=6 -> 32 + 2*64 (planes 19,20);
// ----          n=7 -> 32 + 3*64 (planes 21-23). Planes 0-18 finish in A/B.
__global__ __launch_bounds__(256) void kernelC(const float* __restrict__ x,
                                               const float* __restrict__ uv,
                                               const float* __restrict__ xyz,
                                               const float* __restrict__ fw1,
                                               const float* __restrict__ fb1,
                                               const float* __restrict__ fw2,
                                               const float* __restrict__ fb2,
                                               float* __restrict__ out) {
    __shared__ float red[8];
    __shared__ int s_last;
    __shared__ float z[32];
    __shared__ float theta[7];
    __shared__ float Tm[12];

    const int t = threadIdx.x;
    int myimg, target;

    if (blockIdx.x < FC1_BLOCKS) {
        const int n = blockIdx.x >> 5;
        const int j = blockIdx.x & 31;
        myimg = n;
        target = (n < 6) ? 32 : ((n == 6) ? (32 + 2 * 64) : (32 + 3 * 64));

        const float4* wrow = reinterpret_cast<const float4*>(fw1 + j * 6760);
        const float4* hrow = reinterpret_cast<const float4*>(g_h2 + n * 6760);
        float s = 0.f;
#pragma unroll 7
        for (int k4 = t; k4 < 1690; k4 += 256) {
            float4 wv = __ldg(wrow + k4);
            float4 hv = hrow[k4];
            s = fmaf(wv.x, hv.x, s);
            s = fmaf(wv.y, hv.y, s);
            s = fmaf(wv.z, hv.z, s);
            s = fmaf(wv.w, hv.w, s);
        }
#pragma unroll
        for (int off = 16; off; off >>= 1) s += __shfl_down_sync(0xffffffffu, s, off);
        if ((t & 31) == 0) red[t >> 5] = s;
        __syncthreads();
        if (t == 0) {
            float v = red[0];
#pragma unroll
            for (int r = 1; r < 8; r++) v += red[r];
            g_z[n * 32 + j] = fmaxf(v + fb1[j], 0.f);
        }
    } else {
        int fblk = blockIdx.x - FC1_BLOCKS;
        int plane = 19 + (fblk >> 6);
        myimg = plane / 3;                         // 19,20 -> 6; 21-23 -> 7
        target = (myimg == 6) ? (32 + 2 * 64) : (32 + 3 * 64);
        fill_planes(x, out + 96, fblk, 19);
    }

    __syncthreads();
    if (t == 0) {
        __threadfence();
        int arrived = atomicAdd(&g_cnt[myimg], 1);
        s_last = (arrived == target - 1);
        if (s_last) g_cnt[myimg] = 0;              // self-reset for graph replay
    }
    __syncthreads();
    if (!s_last) return;
    __threadfence();                               // acquire g_z + fills

    const int n = myimg;
    if (t < 32) z[t] = g_z[n * 32 + t];
    __syncthreads();
    if (t < 7) {
        float a = fb2[t];
#pragma unroll
        for (int jj = 0; jj < 32; jj++) a = fmaf(fw2[t * 32 + jj], z[jj], a);
        theta[t] = a;
    }
    __syncthreads();
    if (t == 0) {
        float s0 = fabsf(theta[0]);
        float vx = theta[1], vy = theta[2], vz = theta[3];
        float ang = sqrtf(vx * vx + vy * vy + vz * vz + 1e-8f);
        float kx = vx / ang, ky = vy / ang, kz = vz / ang;
        float sn = sinf(ang);
        float cc = 1.0f - cosf(ang);
        float K[9] = {0.f, -kz, ky,  kz, 0.f, -kx,  -ky, kx, 0.f};
#pragma unroll
        for (int i = 0; i < 3; i++) {
#pragma unroll
            for (int jj = 0; jj < 3; jj++) {
                float kk = 0.f;
#pragma unroll
                for (int m = 0; m < 3; m++) kk += K[i * 3 + m] * K[m * 3 + jj];
                Tm[i * 4 + jj] = (((i == jj) ? 1.f : 0.f) + sn * K[i * 3 + jj] + cc * kk) * s0;
            }
            Tm[i * 4 + 3] = theta[4 + i];
        }
    }
    __syncthreads();

    if (t < 12) out[n * 12 + t] = Tm[t];

#pragma unroll
    for (int k = 0; k < 4; k++) {
        int p = k * 256 + t;
        float X = xyz[p * 3 + 0], Y = xyz[p * 3 + 1], Z = xyz[p * 3 + 2];
        float p0 = Tm[0] * X + Tm[1] * Y + Tm[2] * Z + Tm[3];
        float p1 = Tm[4] * X + Tm[5] * Y + Tm[6] * Z + Tm[7];

        float xs = p0 / (float)IMGW * 2.0f - 1.0f;
        float ys = -(p1 / (float)IMGW * 2.0f - 1.0f);

        float ix = ((xs + 1.0f) * (float)IMGW - 1.0f) * 0.5f;
        float iy = ((ys + 1.0f) * (float)IMGW - 1.0f) * 0.5f;

        float ix0f = floorf(ix), iy0f = floorf(iy);
        float ix1f = ix0f + 1.0f, iy1f = iy0f + 1.0f;
        float wx1 = ix - ix0f, wx0 = 1.0f - wx1;
        float wy1 = iy - iy0f, wy0 = 1.0f - wy1;

        bool vx0 = (ix0f >= 0.f) && (ix0f < (float)IMGW);
        bool vx1 = (ix1f >= 0.f) && (ix1f < (float)IMGW);
        bool vy0 = (iy0f >= 0.f) && (iy0f < (float)IMGW);
        bool vy1 = (iy1f >= 0.f) && (iy1f < (float)IMGW);

        int ii0 = (int)fminf(fmaxf(ix0f, 0.f), (float)(IMGW - 1));
        int ii1 = (int)fminf(fmaxf(ix1f, 0.f), (float)(IMGW - 1));
        int jj0 = (int)fminf(fmaxf(iy0f, 0.f), (float)(IMGW - 1));
        int jj1 = (int)fminf(fmaxf(iy1f, 0.f), (float)(IMGW - 1));

        int pxg = (int)floorf(uv[p * 2 + 0] * (float)TGRID);
        int pyg = (int)floorf(uv[p * 2 + 1] * (float)TGRID);
        if (pxg < 0 || pxg >= TGRID || pyg < 0 || pyg >= TGRID) continue;

        float w00 = wy0 * wx0, w01 = wy0 * wx1, w10 = wy1 * wx0, w11 = wy1 * wx1;

#pragma unroll
        for (int c = 0; c < 3; c++) {
            const float* base = x + ((size_t)(n * 3 + c)) * IMGW * IMGW;
            float v00 = (vy0 && vx0) ? __ldg(base + jj0 * IMGW + ii0) : 0.f;
            float v01 = (vy0 && vx1) ? __ldg(base + jj0 * IMGW + ii1) : 0.f;
            float v10 = (vy1 && vx0) ? __ldg(base + jj1 * IMGW + ii0) : 0.f;
            float v11 = (vy1 && vx1) ? __ldg(base + jj1 * IMGW + ii1) : 0.f;
            float val = v00 * w00 + v01 * w01 + v10 * w10 + v11 * w11;
            out[96 + (((size_t)(n * 3 + c)) << 20) + (size_t)pxg * TGRID + pyg] = val;
        }
    }
}

extern "C" void kernel_launch(void* const* d_in, const int* in_sizes, int n_in,
                              void* d_out, int out_size) {
    const float* x   = (const float*)d_in[0];
    const float* uv  = (const float*)d_in[1];
    const float* xyz = (const float*)d_in[2];
    const float* w1  = (const float*)d_in[3];
    const float* b1  = (const float*)d_in[4];
    const float* w2  = (const float*)d_in[5];
    const float* b2  = (const float*)d_in[6];
    const float* fw1 = (const float*)d_in[7];
    const float* fb1 = (const float*)d_in[8];
    const float* fw2 = (const float*)d_in[9];
    const float* fb2 = (const float*)d_in[10];
    float* out = (float*)d_out;

    kernelA<<<C1_BLOCKS + FILL_A, 256>>>(x, w1, b1, out + 96);
    kernelB<<<C2_BLOCKS + FILL_B + PREF_BLOCKS, 256>>>(x, w2, b2, fw1, out + 96);
    kernelC<<<FC1_BLOCKS + FILL_C, 256>>>(x, uv, xyz, fw1, fb1, fw2, fb2, out);
}

// round 17
// speedup vs baseline: 1.0566x; 1.0566x over previous
#include <cuda_runtime.h>
#include <math.h>

#define NB 8
#define IMGW 120
#define TGRID 1024
#define PPTS 1024

#define C1_THREADS (NB * 2 * 57 * 57)
#define C1_BLOCKS ((C1_THREADS + 255) / 256)     // 204 (4 oc per thread)
#define C2_THREADS (NB * 10 * 26 * 26)           // 54080
#define C2_BLOCKS ((C2_THREADS + 255) / 256)     // 212
#define FC1_BLOCKS 256

#define FILL_A (11 * 64)                          // planes 0-10 in node A
#define FILL_BC (13 * 64)                         // planes 11-23 in node BC

#define H1_STRIDE 58

// scratch (no allocations allowed)
__device__ float g_h1[NB * 8 * 57 * H1_STRIDE];
__device__ float g_h2[NB * 10 * 26 * 26];
__device__ float g_z[NB * 32];
__device__ int   g_c2[NB];                        // conv2-done per image (self-reset)
__device__ int   g_cnt[NB];                       // scatter gate per image (self-reset)

// proven fill: 64 blocks per plane, strided float4 stores
__device__ __forceinline__ void fill_planes(const float* __restrict__ x,
                                            float* __restrict__ out96,
                                            int fblk, int plane_base) {
    int plane = plane_base + (fblk >> 6);
    if (plane >= 24) return;
    int b = fblk & 63;
    const float* xb = x + (size_t)plane * IMGW * IMGW;
    float cst = 0.25f * (__ldg(xb + 59 * IMGW + 59) + __ldg(xb + 59 * IMGW + 60) +
                         __ldg(xb + 60 * IMGW + 59) + __ldg(xb + 60 * IMGW + 60));
    float4 v = make_float4(cst, cst, cst, cst);
    float4* o = reinterpret_cast<float4*>(out96 + (size_t)plane * TGRID * TGRID);
    const int stride = 64 * 256;
#pragma unroll 4
    for (int i = b * 256 + threadIdx.x; i < (TGRID * TGRID / 4); i += stride)
        o[i] = v;
}

// ---------------- kernel A: conv1 (4 oc/thread) || fill planes 0-10 ----------
__global__ __launch_bounds__(256) void kernelA(const float* __restrict__ x,
                                               const float* __restrict__ w,
                                               const float* __restrict__ b,
                                               float* __restrict__ out96) {
    if (blockIdx.x >= C1_BLOCKS) {
        fill_planes(x, out96, blockIdx.x - C1_BLOCKS, 0);
        return;
    }

    __shared__ float ws[8 * 3 * 49];
    __shared__ float bs[8];
    for (int i = threadIdx.x; i < 8 * 3 * 49; i += 256) ws[i] = w[i];
    if (threadIdx.x < 8) bs[threadIdx.x] = b[threadIdx.x];
    __syncthreads();

    int idx = blockIdx.x * 256 + threadIdx.x;
    if (idx >= C1_THREADS) return;
    int px  = idx % 57;
    int py  = (idx / 57) % 57;
    int ocg = (idx / 3249) & 1;
    int n   = idx / 6498;

    float acc[4][4];
#pragma unroll
    for (int oc = 0; oc < 4; oc++)
        acc[oc][0] = acc[oc][1] = acc[oc][2] = acc[oc][3] = 0.f;

    const float* xb = x + (size_t)n * 3 * IMGW * IMGW;
    for (int ic = 0; ic < 3; ic++) {
        const float* xc = xb + ic * IMGW * IMGW + (2 * py) * IMGW + 2 * px;
#pragma unroll
        for (int wy = 0; wy < 8; wy++) {
            const float2* row = reinterpret_cast<const float2*>(xc + wy * IMGW);
            float v[8];
#pragma unroll
            for (int j = 0; j < 4; j++) {
                float2 t = __ldg(row + j);
                v[2 * j] = t.x; v[2 * j + 1] = t.y;
            }
#pragma unroll
            for (int oc = 0; oc < 4; oc++) {
                const float* wr = ws + ((ocg * 4 + oc) * 3 + ic) * 49;
                if (wy < 7) {
#pragma unroll
                    for (int kx = 0; kx < 7; kx++) {
                        float wv = wr[wy * 7 + kx];
                        acc[oc][0] = fmaf(wv, v[kx], acc[oc][0]);
                        acc[oc][1] = fmaf(wv, v[kx + 1], acc[oc][1]);
                    }
                }
                if (wy >= 1) {
#pragma unroll
                    for (int kx = 0; kx < 7; kx++) {
                        float wv = wr[(wy - 1) * 7 + kx];
                        acc[oc][2] = fmaf(wv, v[kx], acc[oc][2]);
                        acc[oc][3] = fmaf(wv, v[kx + 1], acc[oc][3]);
                    }
                }
            }
        }
    }
#pragma unroll
    for (int oc = 0; oc < 4; oc++) {
        int woc = ocg * 4 + oc;
        float m = fmaxf(fmaxf(acc[oc][0], acc[oc][1]), fmaxf(acc[oc][2], acc[oc][3]));
        g_h1[((n * 8 + woc) * 57 + py) * H1_STRIDE + px] = fmaxf(m + bs[woc], 0.f);
    }
}

// ---- kernel BC: conv2 (bids 0-211) -> fc1 (212-467, gated on conv2) ->
// ---- gated scatter; fill planes 11-23 (bids 468+). Single node.
__global__ __launch_bounds__(256) void kernelBC(const float* __restrict__ x,
                                                const float* __restrict__ uv,
                                                const float* __restrict__ xyz,
                                                const float* __restrict__ w2,
                                                const float* __restrict__ b2,
                                                const float* __restrict__ fw1,
                                                const float* __restrict__ fb1,
                                                const float* __restrict__ fw2,
                                                const float* __restrict__ fb2,
                                                float* __restrict__ out) {
    __shared__ float red[8];
    __shared__ int s_last;
    __shared__ float z[32];
    __shared__ float theta[7];
    __shared__ float Tm[12];
    __shared__ float ws[10 * 8 * 25];
    __shared__ float bs[10];

    const int t = threadIdx.x;
    const int bid = blockIdx.x;
    int myimg = -1, target = 0;

    if (bid < C2_BLOCKS) {
        // ================= conv2 =================
        for (int i = t; i < 2000; i += 256) ws[i] = w2[i];
        if (t < 10) bs[t] = b2[t];
        __syncthreads();

        int idx = bid * 256 + t;
        if (idx < C2_THREADS) {
            int px = idx % 26;
            int py = (idx / 26) % 26;
            int oc = (idx / 676) % 10;
            int n  = idx / 6760;

            float a0 = 0.f, a1 = 0.f, a2 = 0.f, a3 = 0.f;
            for (int ic = 0; ic < 8; ic++) {
                const float* xc = g_h1 + ((n * 8 + ic) * 57 + 2 * py) * H1_STRIDE + 2 * px;
                const float* wr = ws + (oc * 8 + ic) * 25;
#pragma unroll
                for (int wy = 0; wy < 6; wy++) {
                    const float2* row = reinterpret_cast<const float2*>(xc + wy * H1_STRIDE);
                    float v[6];
#pragma unroll
                    for (int j = 0; j < 3; j++) {
                        float2 tv = row[j];
                        v[2 * j] = tv.x; v[2 * j + 1] = tv.y;
                    }
                    if (wy < 5) {
#pragma unroll
                        for (int kx = 0; kx < 5; kx++) {
                            float wv = wr[wy * 5 + kx];
                            a0 = fmaf(wv, v[kx], a0);
                            a1 = fmaf(wv, v[kx + 1], a1);
                        }
                    }
                    if (wy >= 1) {
#pragma unroll
                        for (int kx = 0; kx < 5; kx++) {
                            float wv = wr[(wy - 1) * 5 + kx];
                            a2 = fmaf(wv, v[kx], a2);
                            a3 = fmaf(wv, v[kx + 1], a3);
                        }
                    }
                }
            }
            float m = fmaxf(fmaxf(a0, a1), fmaxf(a2, a3));
            g_h2[idx] = fmaxf(m + bs[oc], 0.f);
        }
        __threadfence();          // make this thread's g_h2 write globally visible
        __syncthreads();
        if (t == 0) {
            int base = bid * 256;
            int lasti = base + 255; if (lasti >= C2_THREADS) lasti = C2_THREADS - 1;
            int n0 = base / 6760, n1 = lasti / 6760;
            atomicAdd(&g_c2[n0], 1);
            if (n1 != n0) atomicAdd(&g_c2[n1], 1);
        }
        return;
    }

    if (bid < C2_BLOCKS + FC1_BLOCKS) {
        // ================= fc1 (gated on conv2 for image n) =================
        const int fcb = bid - C2_BLOCKS;
        const int n = fcb >> 5;
        const int j = fcb & 31;
        myimg = n;
        target = (n <= 2) ? 32 : ((n == 3) ? (32 + 1 * 64) : (32 + 3 * 64));

        // preload this block's fw1 row into registers WHILE waiting on conv2
        const float4* wrow = reinterpret_cast<const float4*>(fw1 + j * 6760);
        float4 wv[7];
#pragma unroll
        for (int i = 0; i < 7; i++) {
            int k4 = t + i * 256;
            wv[i] = (k4 < 1690) ? __ldg(wrow + k4) : make_float4(0.f, 0.f, 0.f, 0.f);
        }

        if (t == 0) {
            int expct = ((6760 * (n + 1) - 1) >> 8) - ((6760 * n) >> 8) + 1;
            while (((volatile int*)g_c2)[n] < expct) { __nanosleep(200); }
        }
        __syncthreads();
        __threadfence();   // acquire conv2's g_h2 writes

        const float4* hrow = reinterpret_cast<const float4*>(g_h2 + n * 6760);
        float s = 0.f;
#pragma unroll
        for (int i = 0; i < 7; i++) {
            int k4 = t + i * 256;
            if (k4 < 1690) {
                float4 hv = hrow[k4];
                s = fmaf(wv[i].x, hv.x, s);
                s = fmaf(wv[i].y, hv.y, s);
                s = fmaf(wv[i].z, hv.z, s);
                s = fmaf(wv[i].w, hv.w, s);
            }
        }
#pragma unroll
        for (int off = 16; off; off >>= 1) s += __shfl_down_sync(0xffffffffu, s, off);
        if ((t & 31) == 0) red[t >> 5] = s;
        __syncthreads();
        if (t == 0) {
            float v = red[0];
#pragma unroll
            for (int r = 1; r < 8; r++) v += red[r];
            g_z[n * 32 + j] = fmaxf(v + fb1[j], 0.f);
        }
    } else {
        // ================= fill planes 11-23 =================
        int fblk = bid - C2_BLOCKS - FC1_BLOCKS;
        int plane = 11 + (fblk >> 6);
        myimg = plane / 3;                   // 11 -> 3; 12-23 -> 4..7
        target = (myimg == 3) ? (32 + 1 * 64) : (32 + 3 * 64);
        fill_planes(x, out + 96, fblk, 11);
    }

    // ---- arrival; unique last block per image runs fc2+Rodrigues+scatter ----
    __syncthreads();
    if (t == 0) {
        __threadfence();
        int arrived = atomicAdd(&g_cnt[myimg], 1);
        s_last = (arrived == target - 1);
        if (s_last) { g_cnt[myimg] = 0; g_c2[myimg] = 0; }   // self-reset
    }
    __syncthreads();
    if (!s_last) return;
    __threadfence();                          // acquire g_z + fills

    const int n = myimg;
    if (t < 32) z[t] = g_z[n * 32 + t];
    __syncthreads();
    if (t < 7) {
        float a = fb2[t];
#pragma unroll
        for (int jj = 0; jj < 32; jj++) a = fmaf(fw2[t * 32 + jj], z[jj], a);
        theta[t] = a;
    }
    __syncthreads();
    if (t == 0) {
        float s0 = fabsf(theta[0]);
        float vx = theta[1], vy = theta[2], vz = theta[3];
        float ang = sqrtf(vx * vx + vy * vy + vz * vz + 1e-8f);
        float kx = vx / ang, ky = vy / ang, kz = vz / ang;
        float sn = sinf(ang);
        float cc = 1.0f - cosf(ang);
        float K[9] = {0.f, -kz, ky,  kz, 0.f, -kx,  -ky, kx, 0.f};
#pragma unroll
        for (int i = 0; i < 3; i++) {
#pragma unroll
            for (int jj = 0; jj < 3; jj++) {
                float kk = 0.f;
#pragma unroll
                for (int m = 0; m < 3; m++) kk += K[i * 3 + m] * K[m * 3 + jj];
                Tm[i * 4 + jj] = (((i == jj) ? 1.f : 0.f) + sn * K[i * 3 + jj] + cc * kk) * s0;
            }
            Tm[i * 4 + 3] = theta[4 + i];
        }
    }
    __syncthreads();

    if (t < 12) out[n * 12 + t] = Tm[t];

#pragma unroll
    for (int k = 0; k < 4; k++) {
        int p = k * 256 + t;
        float X = xyz[p * 3 + 0], Y = xyz[p * 3 + 1], Z = xyz[p * 3 + 2];
        float p0 = Tm[0] * X + Tm[1] * Y + Tm[2] * Z + Tm[3];
        float p1 = Tm[4] * X + Tm[5] * Y + Tm[6] * Z + Tm[7];

        float xs = p0 / (float)IMGW * 2.0f - 1.0f;
        float ys = -(p1 / (float)IMGW * 2.0f - 1.0f);

        float ix = ((xs + 1.0f) * (float)IMGW - 1.0f) * 0.5f;
        float iy = ((ys + 1.0f) * (float)IMGW - 1.0f) * 0.5f;

        float ix0f = floorf(ix), iy0f = floorf(iy);
        float ix1f = ix0f + 1.0f, iy1f = iy0f + 1.0f;
        float wx1 = ix - ix0f, wx0 = 1.0f - wx1;
        float wy1 = iy - iy0f, wy0 = 1.0f - wy1;

        bool vx0 = (ix0f >= 0.f) && (ix0f < (float)IMGW);
        bool vx1 = (ix1f >= 0.f) && (ix1f < (float)IMGW);
        bool vy0 = (iy0f >= 0.f) && (iy0f < (float)IMGW);
        bool vy1 = (iy1f >= 0.f) && (iy1f < (float)IMGW);

        int ii0 = (int)fminf(fmaxf(ix0f, 0.f), (float)(IMGW - 1));
        int ii1 = (int)fminf(fmaxf(ix1f, 0.f), (float)(IMGW - 1));
        int jj0 = (int)fminf(fmaxf(iy0f, 0.f), (float)(IMGW - 1));
        int jj1 = (int)fminf(fmaxf(iy1f, 0.f), (float)(IMGW - 1));

        int pxg = (int)floorf(uv[p * 2 + 0] * (float)TGRID);
        int pyg = (int)floorf(uv[p * 2 + 1] * (float)TGRID);
        if (pxg < 0 || pxg >= TGRID || pyg < 0 || pyg >= TGRID) continue;

        float w00 = wy0 * wx0, w01 = wy0 * wx1, w10 = wy1 * wx0, w11 = wy1 * wx1;

#pragma unroll
        for (int c = 0; c < 3; c++) {
            const float* base = x + ((size_t)(n * 3 + c)) * IMGW * IMGW;
            float v00 = (vy0 && vx0) ? __ldg(base + jj0 * IMGW + ii0) : 0.f;
            float v01 = (vy0 && vx1) ? __ldg(base + jj0 * IMGW + ii1) : 0.f;
            float v10 = (vy1 && vx0) ? __ldg(base + jj1 * IMGW + ii0) : 0.f;
            float v11 = (vy1 && vx1) ? __ldg(base + jj1 * IMGW + ii1) : 0.f;
            float val = v00 * w00 + v01 * w01 + v10 * w10 + v11 * w11;
            out[96 + (((size_t)(n * 3 + c)) << 20) + (size_t)pxg * TGRID + pyg] = val;
        }
    }
}

extern "C" void kernel_launch(void* const* d_in, const int* in_sizes, int n_in,
                              void* d_out, int out_size) {
    const float* x   = (const float*)d_in[0];
    const float* uv  = (const float*)d_in[1];
    const float* xyz = (const float*)d_in[2];
    const float* w1  = (const float*)d_in[3];
    const float* b1  = (const float*)d_in[4];
    const float* w2  = (const float*)d_in[5];
    const float* b2  = (const float*)d_in[6];
    const float* fw1 = (const float*)d_in[7];
    const float* fb1 = (const float*)d_in[8];
    const float* fw2 = (const float*)d_in[9];
    const float* fb2 = (const float*)d_in[10];
    float* out = (float*)d_out;

    kernelA<<<C1_BLOCKS + FILL_A, 256>>>(x, w1, b1, out + 96);
    kernelBC<<<C2_BLOCKS + FC1_BLOCKS + FILL_BC, 256>>>(x, uv, xyz, w2, b2,
                                                        fw1, fb1, fw2, fb2, out);
}